// round 14
// baseline (speedup 1.0000x reference)
#include <cuda_runtime.h>
#include <cuda_fp16.h>
#include <cstdint>
#include <math.h>

// ---------------------------------------------------------------------------
// Problem constants
// ---------------------------------------------------------------------------
#define SEQ     4096
#define DIM     2048
#define NHEADS  16
#define HDIM    128
#define QKV_N   6144

// ---------------------------------------------------------------------------
// Scratch (device globals; allocation forbidden)
// ---------------------------------------------------------------------------
__device__ __align__(16) __half g_xh   [(size_t)SEQ * DIM];
__device__ __align__(16) __half g_wqkvT[(size_t)QKV_N * DIM];   // Wqkv^T (Q-third pre-scaled by log2e/sqrt(d))
__device__ __align__(16) __half g_woT  [(size_t)DIM * DIM];
__device__ __align__(16) __half g_xqkv [(size_t)SEQ * QKV_N];
__device__ __align__(16) __half g_xo   [(size_t)SEQ * DIM];

// ---------------------------------------------------------------------------
// Helpers
// ---------------------------------------------------------------------------
__device__ __forceinline__ void mma_f16(float* c, const uint32_t* a, const uint32_t* b) {
    asm volatile(
        "mma.sync.aligned.m16n8k16.row.col.f32.f16.f16.f32 "
        "{%0,%1,%2,%3}, {%4,%5,%6,%7}, {%8,%9}, {%0,%1,%2,%3};"
        : "+f"(c[0]), "+f"(c[1]), "+f"(c[2]), "+f"(c[3])
        : "r"(a[0]), "r"(a[1]), "r"(a[2]), "r"(a[3]), "r"(b[0]), "r"(b[1]));
}

__device__ __forceinline__ void ldsm_x4(uint32_t* r, uint32_t addr) {
    asm volatile("ldmatrix.sync.aligned.m8n8.x4.shared.b16 {%0,%1,%2,%3}, [%4];"
                 : "=r"(r[0]), "=r"(r[1]), "=r"(r[2]), "=r"(r[3]) : "r"(addr));
}
__device__ __forceinline__ void ldsm_x4_t(uint32_t* r, uint32_t addr) {
    asm volatile("ldmatrix.sync.aligned.m8n8.x4.trans.shared.b16 {%0,%1,%2,%3}, [%4];"
                 : "=r"(r[0]), "=r"(r[1]), "=r"(r[2]), "=r"(r[3]) : "r"(addr));
}

__device__ __forceinline__ void cp_async16(uint32_t dst, const void* src) {
    asm volatile("cp.async.cg.shared.global [%0], [%1], 16;" :: "r"(dst), "l"(src));
}
__device__ __forceinline__ void cp_commit() { asm volatile("cp.async.commit_group;"); }
template<int N> __device__ __forceinline__ void cp_wait() {
    asm volatile("cp.async.wait_group %0;" :: "n"(N));
}

// Single-instruction exp2 on the MUFU pipe; scores pre-scaled by log2e.
__device__ __forceinline__ float ex2(float x) {
    float r;
    asm("ex2.approx.f32 %0, %1;" : "=f"(r) : "f"(x));
    return r;
}

// ---------------------------------------------------------------------------
// Prep kernels
// ---------------------------------------------------------------------------
__global__ void f2h_kernel(const float* __restrict__ in, __half* __restrict__ out, int n4)
{
    int i = blockIdx.x * blockDim.x + threadIdx.x;
    if (i < n4) {
        float4 v = ((const float4*)in)[i];
        __half2* o = (__half2*)out + 2 * (size_t)i;
        o[0] = __floats2half2_rn(v.x, v.y);
        o[1] = __floats2half2_rn(v.z, v.w);
    }
}

__global__ void transpose_h_kernel(const float* __restrict__ W, __half* __restrict__ Wt,
                                   int K, int N, int scaleLimit, float scale)
{
    __shared__ float tile[32][33];
    const int n0 = blockIdx.x * 32;
    const int k0 = blockIdx.y * 32;
    const int tx = threadIdx.x, ty = threadIdx.y;
#pragma unroll
    for (int dy = ty; dy < 32; dy += 8)
        tile[dy][tx] = W[(size_t)(k0 + dy) * N + n0 + tx];
    __syncthreads();
#pragma unroll
    for (int dy = ty; dy < 32; dy += 8) {
        int n = n0 + dy;
        float s = (n < scaleLimit) ? scale : 1.0f;
        Wt[(size_t)n * K + k0 + tx] = __float2half_rn(tile[tx][dy] * s);
    }
}

// ---------------------------------------------------------------------------
// FP16 GEMM "big": CTA 128x128, 512 threads (16 warps, warp tile 32x32),
// K-chunk 64 halves, 2-stage cp.async, one barrier/iter, 3 CTAs/SM = 48 warps.
// Used for GEMM1 (large grid). Rows 144B padded.
// ---------------------------------------------------------------------------
#define GKH 64
#define GB_ROWS 256                         // 128 A + 128 B rows
#define GB_STG (GB_ROWS * 144)              // 36864 B per stage
#define GEMMB_SMEM_BYTES (2 * GB_STG)       // 73728 B -> 3 CTAs/SM

__global__ __launch_bounds__(512, 3)
void gemm_f16_big(const __half* __restrict__ A, const __half* __restrict__ Bt,
                  __half* __restrict__ C, int N, int K)
{
    extern __shared__ char smc[];
    const uint32_t sb = (uint32_t)__cvta_generic_to_shared(smc);

    const int tid  = threadIdx.x;
    const int lane = tid & 31;
    const int wid  = tid >> 5;           // 0..15
    const int g    = lane >> 2;
    const int tig  = lane & 3;
    const int wM   = wid & 3;            // 0..3 -> 32-row band
    const int wN   = wid >> 2;           // 0..3 -> 32-col band
    const int bm = blockIdx.y * 128;
    const int bn = blockIdx.x * 128;

    // cp.async: 512 threads cover 256 rows x 8 chunks; thread -> row r0c (+64j), chunk tid&7
    const int r0c = tid >> 3;            // 0..63
    const int co  = (tid & 7) * 8;       // halves offset
    const __half* Abase = A  + (size_t)(bm + r0c) * K + co;
    const __half* Bbase = Bt + (size_t)(bn + r0c) * K + co;
    const uint32_t cdst = sb + (uint32_t)r0c * 144u + (uint32_t)(tid & 7) * 16u;

    const int arow_l = (lane & 7) + ((lane >> 3) & 1) * 8;
    const uint32_t a_lm0 = sb + (uint32_t)(32 * wM + arow_l) * 144u
                              + (uint32_t)(lane >> 4) * 16u;
    const int brow_l = (lane >> 4) * 8 + (lane & 7);
    const uint32_t b_lm0 = sb + (uint32_t)(128 + 32 * wN + brow_l) * 144u
                              + (uint32_t)((lane >> 3) & 1) * 16u;

    float acc[8][4];
#pragma unroll
    for (int i = 0; i < 8; i++) { acc[i][0] = acc[i][1] = acc[i][2] = acc[i][3] = 0.f; }

    const int nIter = K / GKH;

#define GEMMB_ISSUE(IT, BUF) do {                                              \
        uint32_t _d = cdst + (uint32_t)((BUF) * GB_STG);                       \
        _Pragma("unroll")                                                      \
        for (int _j = 0; _j < 2; _j++)                                         \
            cp_async16(_d + _j * (64u * 144u),                                 \
                       Abase + (size_t)(64 * _j) * K + (IT) * GKH);            \
        _Pragma("unroll")                                                      \
        for (int _j = 0; _j < 2; _j++)                                         \
            cp_async16(_d + (2 + _j) * (64u * 144u),                           \
                       Bbase + (size_t)(64 * _j) * K + (IT) * GKH);            \
        cp_commit();                                                           \
    } while (0)

    GEMMB_ISSUE(0, 0);

    for (int it = 0; it < nIter; ++it) {
        cp_wait<0>();
        __syncthreads();                 // data visible + other buffer free

        if (it + 1 < nIter) GEMMB_ISSUE(it + 1, (it + 1) & 1);

        const uint32_t a_lm = a_lm0 + (uint32_t)((it & 1) * GB_STG);
        const uint32_t b_lm = b_lm0 + (uint32_t)((it & 1) * GB_STG);

#pragma unroll
        for (int ks = 0; ks < 4; ks++) {
            uint32_t af[2][4], bf[4][2];
#pragma unroll
            for (int mt = 0; mt < 2; mt++)
                ldsm_x4(af[mt], a_lm + (uint32_t)(mt * 16 * 144 + ks * 32));
#pragma unroll
            for (int ng = 0; ng < 2; ng++) {
                uint32_t t4[4];
                ldsm_x4(t4, b_lm + (uint32_t)(ng * 16 * 144 + ks * 32));
                bf[2 * ng][0]     = t4[0];
                bf[2 * ng][1]     = t4[1];
                bf[2 * ng + 1][0] = t4[2];
                bf[2 * ng + 1][1] = t4[3];
            }
#pragma unroll
            for (int mt = 0; mt < 2; mt++)
#pragma unroll
                for (int nt = 0; nt < 4; nt++)
                    mma_f16(acc[mt * 4 + nt], af[mt], bf[nt]);
        }
    }

    // fp16 output (GEMM1 feeds attention)
#pragma unroll
    for (int mt = 0; mt < 2; mt++) {
        const int r0 = bm + 32 * wM + mt * 16 + g;
#pragma unroll
        for (int nt = 0; nt < 4; nt++) {
            const int col = bn + 32 * wN + nt * 8 + 2 * tig;
            *(__half2*)(C + (size_t)r0 * N + col) =
                __floats2half2_rn(acc[mt * 4 + nt][0], acc[mt * 4 + nt][1]);
            *(__half2*)(C + (size_t)(r0 + 8) * N + col) =
                __floats2half2_rn(acc[mt * 4 + nt][2], acc[mt * 4 + nt][3]);
        }
    }
#undef GEMMB_ISSUE
}

// ---------------------------------------------------------------------------
// FP16 GEMM (R11 version, kept for GEMM2): CTA 128x64, 256 threads, 4 CTAs/SM.
// ---------------------------------------------------------------------------
#define GROWS 192
#define GSTG_B (GROWS * 144)
#define GEMM_SMEM_BYTES (2 * GSTG_B)

__global__ __launch_bounds__(256, 4)
void gemm_f16(const __half* __restrict__ A, const __half* __restrict__ Bt,
              void* __restrict__ Cv, int N, int K, int out_half)
{
    extern __shared__ char smc[];
    const uint32_t sb = (uint32_t)__cvta_generic_to_shared(smc);

    const int tid  = threadIdx.x;
    const int lane = tid & 31;
    const int wid  = tid >> 5;
    const int g    = lane >> 2;
    const int tig  = lane & 3;
    const int wM   = wid & 3;
    const int wN   = wid >> 2;
    const int bm = blockIdx.y * 128;
    const int bn = blockIdx.x * 64;

    const int r0c = tid >> 3;
    const int co  = (tid & 7) * 8;
    const __half* Abase = A  + (size_t)(bm + r0c) * K + co;
    const __half* Bbase = Bt + (size_t)(bn + r0c) * K + co;
    const uint32_t cdst = sb + (uint32_t)r0c * 144u + (uint32_t)(tid & 7) * 16u;

    const int arow_l = (lane & 7) + ((lane >> 3) & 1) * 8;
    const uint32_t a_lm0 = sb + (uint32_t)(32 * wM + arow_l) * 144u
                              + (uint32_t)(lane >> 4) * 16u;
    const int brow_l = (lane >> 4) * 8 + (lane & 7);
    const uint32_t b_lm0 = sb + (uint32_t)(128 + 32 * wN + brow_l) * 144u
                              + (uint32_t)((lane >> 3) & 1) * 16u;

    float acc[8][4];
#pragma unroll
    for (int i = 0; i < 8; i++) { acc[i][0] = acc[i][1] = acc[i][2] = acc[i][3] = 0.f; }

    const int nIter = K / GKH;

#define GEMM_ISSUE(IT, BUF) do {                                               \
        uint32_t _d = cdst + (uint32_t)((BUF) * GSTG_B);                       \
        _Pragma("unroll")                                                      \
        for (int _j = 0; _j < 4; _j++)                                         \
            cp_async16(_d + _j * (32u * 144u),                                 \
                       Abase + (size_t)(32 * _j) * K + (IT) * GKH);            \
        _Pragma("unroll")                                                      \
        for (int _j = 0; _j < 2; _j++)                                         \
            cp_async16(_d + (4 + _j) * (32u * 144u),                           \
                       Bbase + (size_t)(32 * _j) * K + (IT) * GKH);            \
        cp_commit();                                                           \
    } while (0)

    GEMM_ISSUE(0, 0);

    for (int it = 0; it < nIter; ++it) {
        cp_wait<0>();
        __syncthreads();

        if (it + 1 < nIter) GEMM_ISSUE(it + 1, (it + 1) & 1);

        const uint32_t a_lm = a_lm0 + (uint32_t)((it & 1) * GSTG_B);
        const uint32_t b_lm = b_lm0 + (uint32_t)((it & 1) * GSTG_B);

#pragma unroll
        for (int ks = 0; ks < 4; ks++) {
            uint32_t af[2][4], bf[4][2];
#pragma unroll
            for (int mt = 0; mt < 2; mt++)
                ldsm_x4(af[mt], a_lm + (uint32_t)(mt * 16 * 144 + ks * 32));
#pragma unroll
            for (int ng = 0; ng < 2; ng++) {
                uint32_t t4[4];
                ldsm_x4(t4, b_lm + (uint32_t)(ng * 16 * 144 + ks * 32));
                bf[2 * ng][0]     = t4[0];
                bf[2 * ng][1]     = t4[1];
                bf[2 * ng + 1][0] = t4[2];
                bf[2 * ng + 1][1] = t4[3];
            }
#pragma unroll
            for (int mt = 0; mt < 2; mt++)
#pragma unroll
                for (int nt = 0; nt < 4; nt++)
                    mma_f16(acc[mt * 4 + nt], af[mt], bf[nt]);
        }
    }

    if (out_half) {
        __half* C = (__half*)Cv;
#pragma unroll
        for (int mt = 0; mt < 2; mt++) {
            const int r0 = bm + 32 * wM + mt * 16 + g;
#pragma unroll
            for (int nt = 0; nt < 4; nt++) {
                const int col = bn + 32 * wN + nt * 8 + 2 * tig;
                *(__half2*)(C + (size_t)r0 * N + col) =
                    __floats2half2_rn(acc[mt * 4 + nt][0], acc[mt * 4 + nt][1]);
                *(__half2*)(C + (size_t)(r0 + 8) * N + col) =
                    __floats2half2_rn(acc[mt * 4 + nt][2], acc[mt * 4 + nt][3]);
            }
        }
    } else {
        float* C = (float*)Cv;
#pragma unroll
        for (int mt = 0; mt < 2; mt++) {
            const int r0 = bm + 32 * wM + mt * 16 + g;
#pragma unroll
            for (int nt = 0; nt < 4; nt++) {
                const int col = bn + 32 * wN + nt * 8 + 2 * tig;
                *(float2*)(C + (size_t)r0 * N + col) =
                    make_float2(acc[mt * 4 + nt][0], acc[mt * 4 + nt][1]);
                *(float2*)(C + (size_t)(r0 + 8) * N + col) =
                    make_float2(acc[mt * 4 + nt][2], acc[mt * 4 + nt][3]);
            }
        }
    }
#undef GEMM_ISSUE
}

// ---------------------------------------------------------------------------
// FP16 flash attention (unchanged from R13): max-free base-2 softmax (ex2),
// one barrier/iter, P/K/V double-buffered, PV(t) || S(t+1). 2 CTAs/SM.
// ---------------------------------------------------------------------------
#define BR 64
#define BC 64
#define NT (SEQ / BC)
#define AQ   0
#define AK0  17408
#define AK1  34816
#define AV0  52224
#define AV1  69632
#define AP0  87040
#define AP1  96256
#define APS  105472
#define ATTN_SMEM_BYTES 106496

__global__ __launch_bounds__(256, 2)
void attn_f16(const __half* __restrict__ xqkv, __half* __restrict__ xo)
{
    extern __shared__ char smc[];
    const uint32_t sb = (uint32_t)__cvta_generic_to_shared(smc);
    float* psum = (float*)(smc + APS);

    const int tid  = threadIdx.x;
    const int lane = tid & 31;
    const int wid  = tid >> 5;
    const int g    = lane >> 2;
    const int tig  = lane & 3;
    const int wM   = wid & 1;
    const int wN   = wid >> 1;

    const int h  = blockIdx.y;
    const int q0 = blockIdx.x * BR;

    const __half* Qg = xqkv + (size_t)q0 * QKV_N + h * HDIM;
    const __half* Kg = xqkv + 2048 + h * HDIM;
    const __half* Vg = xqkv + 4096 + h * HDIM;

    const int crow = tid >> 2;
    const int cbo  = (tid & 3) * 64;

    const int arow_l = (lane & 7) + ((lane >> 3) & 1) * 8;
    const uint32_t lpA272 = (uint32_t)arow_l * 272u + (uint32_t)(lane >> 4) * 16u;
    const uint32_t lpA144 = (uint32_t)arow_l * 144u + (uint32_t)(lane >> 4) * 16u;
    const int brow_l = (lane >> 4) * 8 + (lane & 7);
    const uint32_t lpB272 = (uint32_t)brow_l * 272u + (uint32_t)((lane >> 3) & 1) * 16u;

    const uint32_t q_lm   = sb + AQ + (uint32_t)(32 * wM) * 272u + lpA272;
    const uint32_t k_lmBo = (uint32_t)(16 * wN) * 272u + lpB272;
    const uint32_t p_lmBo = (uint32_t)(32 * wM) * 144u + lpA144;

    float sacc[4][4];
    float oacc[8][4];
    float lacc[2][2];
#pragma unroll
    for (int i = 0; i < 8; i++) { oacc[i][0] = oacc[i][1] = oacc[i][2] = oacc[i][3] = 0.f; }
    lacc[0][0] = lacc[0][1] = lacc[1][0] = lacc[1][1] = 0.f;

    auto compute_S = [&](uint32_t k_lm) {
#pragma unroll
        for (int i = 0; i < 4; i++) { sacc[i][0] = sacc[i][1] = sacc[i][2] = sacc[i][3] = 0.f; }
#pragma unroll
        for (int ks = 0; ks < 8; ks++) {
            uint32_t af[2][4], bf[2][2];
#pragma unroll
            for (int mt = 0; mt < 2; mt++)
                ldsm_x4(af[mt], q_lm + (uint32_t)(mt * 16 * 272 + ks * 32));
            {
                uint32_t t4[4];
                ldsm_x4(t4, k_lm + (uint32_t)(ks * 32));
                bf[0][0] = t4[0]; bf[0][1] = t4[1];
                bf[1][0] = t4[2]; bf[1][1] = t4[3];
            }
#pragma unroll
            for (int mt = 0; mt < 2; mt++)
#pragma unroll
                for (int nt = 0; nt < 2; nt++)
                    mma_f16(sacc[mt * 2 + nt], af[mt], bf[nt]);
        }
    };

    {
        const __half* qs = Qg + (size_t)crow * QKV_N + cbo / 2;
        const __half* ks = Kg + (size_t)crow * QKV_N + cbo / 2;
        const uint32_t qd = sb + AQ  + (uint32_t)crow * 272u + cbo;
        const uint32_t kd = sb + AK0 + (uint32_t)crow * 272u + cbo;
#pragma unroll
        for (int j = 0; j < 4; j++) cp_async16(qd + j * 16u, qs + j * 8);
#pragma unroll
        for (int j = 0; j < 4; j++) cp_async16(kd + j * 16u, ks + j * 8);
        cp_commit();

        const __half* vs = Vg + (size_t)crow * QKV_N + cbo / 2;
        const __half* k1 = Kg + (size_t)(BC + crow) * QKV_N + cbo / 2;
        const uint32_t vd = sb + AV0 + (uint32_t)crow * 272u + cbo;
        const uint32_t k1d = sb + AK1 + (uint32_t)crow * 272u + cbo;
#pragma unroll
        for (int j = 0; j < 4; j++) cp_async16(vd + j * 16u, vs + j * 8);
#pragma unroll
        for (int j = 0; j < 4; j++) cp_async16(k1d + j * 16u, k1 + j * 8);
        cp_commit();
    }

    cp_wait<1>();
    __syncthreads();

    compute_S(sb + AK0 + k_lmBo);

    for (int t = 0; t < NT; ++t) {
        const int cur = t & 1, nxt = cur ^ 1;
        const uint32_t pbuf = (cur ? AP1 : AP0);

        {
            char* pbase = smc + pbuf;
#pragma unroll
            for (int mt = 0; mt < 2; mt++)
#pragma unroll
                for (int hh = 0; hh < 2; hh++) {
                    const int r = 32 * wM + 16 * mt + g + 8 * hh;
                    float e0 = ex2(sacc[2 * mt][2 * hh]);
                    float e1 = ex2(sacc[2 * mt][2 * hh + 1]);
                    float e2 = ex2(sacc[2 * mt + 1][2 * hh]);
                    float e3 = ex2(sacc[2 * mt + 1][2 * hh + 1]);
                    lacc[mt][hh] += (e0 + e1) + (e2 + e3);
                    char* pr = pbase + (size_t)r * 144;
                    *(__half2*)(pr + (16 * wN + 2 * tig) * 2)     = __floats2half2_rn(e0, e1);
                    *(__half2*)(pr + (16 * wN + 8 + 2 * tig) * 2) = __floats2half2_rn(e2, e3);
                }
        }

        cp_wait<0>();
        __syncthreads();

        if (t + 1 < NT) {
            const __half* vs = Vg + (size_t)((t + 1) * BC + crow) * QKV_N + cbo / 2;
            const uint32_t vd = sb + (nxt ? AV1 : AV0) + (uint32_t)crow * 272u + cbo;
#pragma unroll
            for (int j = 0; j < 4; j++) cp_async16(vd + j * 16u, vs + j * 8);
            if (t + 2 < NT) {
                const __half* ks = Kg + (size_t)((t + 2) * BC + crow) * QKV_N + cbo / 2;
                const uint32_t kd = sb + (cur ? AK1 : AK0) + (uint32_t)crow * 272u + cbo;
#pragma unroll
                for (int j = 0; j < 4; j++) cp_async16(kd + j * 16u, ks + j * 8);
            }
            cp_commit();
        }

        const uint32_t p_lm = sb + pbuf + p_lmBo;
        const uint32_t v_lm = sb + (cur ? AV1 : AV0) + lpA272;
#pragma unroll
        for (int ks = 0; ks < 4; ks++) {
            uint32_t paf[2][4], vbf[4][2];
#pragma unroll
            for (int mt = 0; mt < 2; mt++)
                ldsm_x4(paf[mt], p_lm + (uint32_t)(mt * 16 * 144 + ks * 32));
#pragma unroll
            for (int ng = 0; ng < 2; ng++) {
                uint32_t t4[4];
                ldsm_x4_t(t4, v_lm + (uint32_t)(ks * 16 * 272 + (32 * wN + ng * 16) * 2));
                vbf[2 * ng][0]     = t4[0];
                vbf[2 * ng][1]     = t4[1];
                vbf[2 * ng + 1][0] = t4[2];
                vbf[2 * ng + 1][1] = t4[3];
            }
#pragma unroll
            for (int mt = 0; mt < 2; mt++)
#pragma unroll
                for (int nt = 0; nt < 4; nt++)
                    mma_f16(oacc[mt * 4 + nt], paf[mt], vbf[nt]);
        }

        if (t + 1 < NT)
            compute_S(sb + (nxt ? AK1 : AK0) + k_lmBo);
    }

#pragma unroll
    for (int mt = 0; mt < 2; mt++)
#pragma unroll
        for (int hh = 0; hh < 2; hh++) {
            float sum = lacc[mt][hh];
            sum += __shfl_xor_sync(0xffffffffu, sum, 1);
            sum += __shfl_xor_sync(0xffffffffu, sum, 2);
            if (tig == 0)
                psum[wN * 64 + 32 * wM + 16 * mt + g + 8 * hh] = sum;
        }
    __syncthreads();

#pragma unroll
    for (int mt = 0; mt < 2; mt++) {
        const int r0 = 32 * wM + 16 * mt + g;
        const float l0 = (psum[r0] + psum[64 + r0]) + (psum[128 + r0] + psum[192 + r0]);
        const float l1 = (psum[r0 + 8] + psum[64 + r0 + 8]) +
                         (psum[128 + r0 + 8] + psum[192 + r0 + 8]);
        const float il0 = 1.f / l0;
        const float il1 = 1.f / l1;
#pragma unroll
        for (int nt = 0; nt < 4; nt++) {
            const int col = h * HDIM + 32 * wN + 8 * nt + 2 * tig;
            *(__half2*)(xo + (size_t)(q0 + r0) * DIM + col) =
                __floats2half2_rn(oacc[mt * 4 + nt][0] * il0, oacc[mt * 4 + nt][1] * il0);
            *(__half2*)(xo + (size_t)(q0 + r0 + 8) * DIM + col) =
                __floats2half2_rn(oacc[mt * 4 + nt][2] * il1, oacc[mt * 4 + nt][3] * il1);
        }
    }
}

// ---------------------------------------------------------------------------
// Launch
// ---------------------------------------------------------------------------
extern "C" void kernel_launch(void* const* d_in, const int* in_sizes, int n_in,
                              void* d_out, int out_size)
{
    const float* x    = (const float*)d_in[0];   // [4096, 2048]
    const float* Wqkv = (const float*)d_in[1];   // [2048, 6144]
    const float* Wo   = (const float*)d_in[2];   // [2048, 2048]
    float* out = (float*)d_out;                  // [4096, 2048]

    __half *xh, *wqkvT, *woT, *xqkv, *xo;
    cudaGetSymbolAddress((void**)&xh,    g_xh);
    cudaGetSymbolAddress((void**)&wqkvT, g_wqkvT);
    cudaGetSymbolAddress((void**)&woT,   g_woT);
    cudaGetSymbolAddress((void**)&xqkv,  g_xqkv);
    cudaGetSymbolAddress((void**)&xo,    g_xo);

    cudaFuncSetAttribute(gemm_f16_big, cudaFuncAttributeMaxDynamicSharedMemorySize,
                         GEMMB_SMEM_BYTES);
    cudaFuncSetAttribute(gemm_f16, cudaFuncAttributeMaxDynamicSharedMemorySize,
                         GEMM_SMEM_BYTES);
    cudaFuncSetAttribute(attn_f16, cudaFuncAttributeMaxDynamicSharedMemorySize,
                         ATTN_SMEM_BYTES);

    // 0) prep: Wq pre-scaled by log2e/sqrt(d) -> base-2 softmax downstream
    f2h_kernel<<<(SEQ * DIM / 4) / 256, 256>>>(x, xh, SEQ * DIM / 4);
    {
        dim3 blk(32, 8);
        transpose_h_kernel<<<dim3(QKV_N / 32, DIM / 32), blk>>>(
            Wqkv, wqkvT, DIM, QKV_N, NHEADS * HDIM,
            0.08838834764831845f * 1.4426950408889634f);
        transpose_h_kernel<<<dim3(DIM / 32, DIM / 32), blk>>>(
            Wo, woT, DIM, DIM, 0, 1.0f);
    }
    // 1) xqkv = x @ Wqkv (fp16 out) — big 128x128 tile, 48 warps/SM
    {
        dim3 grid(QKV_N / 128, SEQ / 128);
        gemm_f16_big<<<grid, 512, GEMMB_SMEM_BYTES>>>(xh, wqkvT, xqkv, QKV_N, DIM);
    }
    // 2) flash attention -> xo (fp16)
    {
        dim3 grid(SEQ / BR, NHEADS);
        attn_f16<<<grid, 256, ATTN_SMEM_BYTES>>>(xqkv, xo);
    }
    // 3) out = xo @ Wo (fp32 out) — 64-wide tile (better wave balance here)
    {
        dim3 grid(DIM / 64, SEQ / 128);
        gemm_f16<<<grid, 256, GEMM_SMEM_BYTES>>>(xo, woT, out, DIM, DIM, 0);
    }
}

// round 16
// speedup vs baseline: 1.8677x; 1.8677x over previous
#include <cuda_runtime.h>
#include <cuda_fp16.h>
#include <cstdint>
#include <math.h>

// ---------------------------------------------------------------------------
// Problem constants
// ---------------------------------------------------------------------------
#define SEQ     4096
#define DIM     2048
#define NHEADS  16
#define HDIM    128
#define QKV_N   6144

// ---------------------------------------------------------------------------
// Scratch (device globals; allocation forbidden)
// ---------------------------------------------------------------------------
__device__ __align__(16) __half g_xh   [(size_t)SEQ * DIM];
__device__ __align__(16) __half g_wqkvT[(size_t)QKV_N * DIM];   // Wqkv^T (Q-third pre-scaled by log2e/sqrt(d))
__device__ __align__(16) __half g_woT  [(size_t)DIM * DIM];
__device__ __align__(16) __half g_xqkv [(size_t)SEQ * QKV_N];
__device__ __align__(16) __half g_xo   [(size_t)SEQ * DIM];

// ---------------------------------------------------------------------------
// Helpers
// ---------------------------------------------------------------------------
__device__ __forceinline__ void mma_f16(float* c, const uint32_t* a, const uint32_t* b) {
    asm volatile(
        "mma.sync.aligned.m16n8k16.row.col.f32.f16.f16.f32 "
        "{%0,%1,%2,%3}, {%4,%5,%6,%7}, {%8,%9}, {%0,%1,%2,%3};"
        : "+f"(c[0]), "+f"(c[1]), "+f"(c[2]), "+f"(c[3])
        : "r"(a[0]), "r"(a[1]), "r"(a[2]), "r"(a[3]), "r"(b[0]), "r"(b[1]));
}

__device__ __forceinline__ void ldsm_x4(uint32_t* r, uint32_t addr) {
    asm volatile("ldmatrix.sync.aligned.m8n8.x4.shared.b16 {%0,%1,%2,%3}, [%4];"
                 : "=r"(r[0]), "=r"(r[1]), "=r"(r[2]), "=r"(r[3]) : "r"(addr));
}
__device__ __forceinline__ void ldsm_x4_t(uint32_t* r, uint32_t addr) {
    asm volatile("ldmatrix.sync.aligned.m8n8.x4.trans.shared.b16 {%0,%1,%2,%3}, [%4];"
                 : "=r"(r[0]), "=r"(r[1]), "=r"(r[2]), "=r"(r[3]) : "r"(addr));
}

__device__ __forceinline__ void cp_async16(uint32_t dst, const void* src) {
    asm volatile("cp.async.cg.shared.global [%0], [%1], 16;" :: "r"(dst), "l"(src));
}
__device__ __forceinline__ void cp_commit() { asm volatile("cp.async.commit_group;"); }
template<int N> __device__ __forceinline__ void cp_wait() {
    asm volatile("cp.async.wait_group %0;" :: "n"(N));
}

// Single-instruction exp2 on the MUFU pipe; scores pre-scaled by log2e.
__device__ __forceinline__ float ex2(float x) {
    float r;
    asm("ex2.approx.f32 %0, %1;" : "=f"(r) : "f"(x));
    return r;
}

// ---------------------------------------------------------------------------
// Prep kernels
// ---------------------------------------------------------------------------
__global__ void f2h_kernel(const float* __restrict__ in, __half* __restrict__ out, int n4)
{
    int i = blockIdx.x * blockDim.x + threadIdx.x;
    if (i < n4) {
        float4 v = ((const float4*)in)[i];
        __half2* o = (__half2*)out + 2 * (size_t)i;
        o[0] = __floats2half2_rn(v.x, v.y);
        o[1] = __floats2half2_rn(v.z, v.w);
    }
}

__global__ void transpose_h_kernel(const float* __restrict__ W, __half* __restrict__ Wt,
                                   int K, int N, int scaleLimit, float scale)
{
    __shared__ float tile[32][33];
    const int n0 = blockIdx.x * 32;
    const int k0 = blockIdx.y * 32;
    const int tx = threadIdx.x, ty = threadIdx.y;
#pragma unroll
    for (int dy = ty; dy < 32; dy += 8)
        tile[dy][tx] = W[(size_t)(k0 + dy) * N + n0 + tx];
    __syncthreads();
#pragma unroll
    for (int dy = ty; dy < 32; dy += 8) {
        int n = n0 + dy;
        float s = (n < scaleLimit) ? scale : 1.0f;
        Wt[(size_t)n * K + k0 + tx] = __float2half_rn(tile[tx][dy] * s);
    }
}

// ---------------------------------------------------------------------------
// FP16 GEMM "big": CTA 128x128, 512 threads (16 warps, warp tile 32x32),
// 2-stage cp.async, one barrier/iter. __launch_bounds__(512,2): 2048 thr/SM
// -> 64-reg cap which FITS the 63-reg body (R14's (512,3) capped at 42 and
// spilled catastrophically). 32 warps/SM, half the L2 traffic of the 64-wide
// tile, half the CTA count.
// ---------------------------------------------------------------------------
#define GKH 64
#define GB_ROWS 256
#define GB_STG (GB_ROWS * 144)             // 36864 B per stage
#define GEMMB_SMEM_BYTES (2 * GB_STG)      // 73728 B -> 2 CTAs/SM

__global__ __launch_bounds__(512, 2)
void gemm_f16_big(const __half* __restrict__ A, const __half* __restrict__ Bt,
                  __half* __restrict__ C, int N, int K)
{
    extern __shared__ char smc[];
    const uint32_t sb = (uint32_t)__cvta_generic_to_shared(smc);

    const int tid  = threadIdx.x;
    const int lane = tid & 31;
    const int wid  = tid >> 5;           // 0..15
    const int g    = lane >> 2;
    const int tig  = lane & 3;
    const int wM   = wid & 3;            // 0..3 -> 32-row band
    const int wN   = wid >> 2;           // 0..3 -> 32-col band
    const int bm = blockIdx.y * 128;
    const int bn = blockIdx.x * 128;

    const int r0c = tid >> 3;            // 0..63
    const int co  = (tid & 7) * 8;
    const __half* Abase = A  + (size_t)(bm + r0c) * K + co;
    const __half* Bbase = Bt + (size_t)(bn + r0c) * K + co;
    const uint32_t cdst = sb + (uint32_t)r0c * 144u + (uint32_t)(tid & 7) * 16u;

    const int arow_l = (lane & 7) + ((lane >> 3) & 1) * 8;
    const uint32_t a_lm0 = sb + (uint32_t)(32 * wM + arow_l) * 144u
                              + (uint32_t)(lane >> 4) * 16u;
    const int brow_l = (lane >> 4) * 8 + (lane & 7);
    const uint32_t b_lm0 = sb + (uint32_t)(128 + 32 * wN + brow_l) * 144u
                              + (uint32_t)((lane >> 3) & 1) * 16u;

    float acc[8][4];
#pragma unroll
    for (int i = 0; i < 8; i++) { acc[i][0] = acc[i][1] = acc[i][2] = acc[i][3] = 0.f; }

    const int nIter = K / GKH;

#define GEMMB_ISSUE(IT, BUF) do {                                              \
        uint32_t _d = cdst + (uint32_t)((BUF) * GB_STG);                       \
        _Pragma("unroll")                                                      \
        for (int _j = 0; _j < 2; _j++)                                         \
            cp_async16(_d + _j * (64u * 144u),                                 \
                       Abase + (size_t)(64 * _j) * K + (IT) * GKH);            \
        _Pragma("unroll")                                                      \
        for (int _j = 0; _j < 2; _j++)                                         \
            cp_async16(_d + (2 + _j) * (64u * 144u),                           \
                       Bbase + (size_t)(64 * _j) * K + (IT) * GKH);            \
        cp_commit();                                                           \
    } while (0)

    GEMMB_ISSUE(0, 0);

    for (int it = 0; it < nIter; ++it) {
        cp_wait<0>();
        __syncthreads();

        if (it + 1 < nIter) GEMMB_ISSUE(it + 1, (it + 1) & 1);

        const uint32_t a_lm = a_lm0 + (uint32_t)((it & 1) * GB_STG);
        const uint32_t b_lm = b_lm0 + (uint32_t)((it & 1) * GB_STG);

#pragma unroll
        for (int ks = 0; ks < 4; ks++) {
            uint32_t af[2][4], bf[4][2];
#pragma unroll
            for (int mt = 0; mt < 2; mt++)
                ldsm_x4(af[mt], a_lm + (uint32_t)(mt * 16 * 144 + ks * 32));
#pragma unroll
            for (int ng = 0; ng < 2; ng++) {
                uint32_t t4[4];
                ldsm_x4(t4, b_lm + (uint32_t)(ng * 16 * 144 + ks * 32));
                bf[2 * ng][0]     = t4[0];
                bf[2 * ng][1]     = t4[1];
                bf[2 * ng + 1][0] = t4[2];
                bf[2 * ng + 1][1] = t4[3];
            }
#pragma unroll
            for (int mt = 0; mt < 2; mt++)
#pragma unroll
                for (int nt = 0; nt < 4; nt++)
                    mma_f16(acc[mt * 4 + nt], af[mt], bf[nt]);
        }
    }

#pragma unroll
    for (int mt = 0; mt < 2; mt++) {
        const int r0 = bm + 32 * wM + mt * 16 + g;
#pragma unroll
        for (int nt = 0; nt < 4; nt++) {
            const int col = bn + 32 * wN + nt * 8 + 2 * tig;
            *(__half2*)(C + (size_t)r0 * N + col) =
                __floats2half2_rn(acc[mt * 4 + nt][0], acc[mt * 4 + nt][1]);
            *(__half2*)(C + (size_t)(r0 + 8) * N + col) =
                __floats2half2_rn(acc[mt * 4 + nt][2], acc[mt * 4 + nt][3]);
        }
    }
#undef GEMMB_ISSUE
}

// ---------------------------------------------------------------------------
// FP16 GEMM (R11 version, for GEMM2): CTA 128x64, 256 threads, 4 CTAs/SM.
// ---------------------------------------------------------------------------
#define GROWS 192
#define GSTG_B (GROWS * 144)
#define GEMM_SMEM_BYTES (2 * GSTG_B)

__global__ __launch_bounds__(256, 4)
void gemm_f16(const __half* __restrict__ A, const __half* __restrict__ Bt,
              void* __restrict__ Cv, int N, int K, int out_half)
{
    extern __shared__ char smc[];
    const uint32_t sb = (uint32_t)__cvta_generic_to_shared(smc);

    const int tid  = threadIdx.x;
    const int lane = tid & 31;
    const int wid  = tid >> 5;
    const int g    = lane >> 2;
    const int tig  = lane & 3;
    const int wM   = wid & 3;
    const int wN   = wid >> 2;
    const int bm = blockIdx.y * 128;
    const int bn = blockIdx.x * 64;

    const int r0c = tid >> 3;
    const int co  = (tid & 7) * 8;
    const __half* Abase = A  + (size_t)(bm + r0c) * K + co;
    const __half* Bbase = Bt + (size_t)(bn + r0c) * K + co;
    const uint32_t cdst = sb + (uint32_t)r0c * 144u + (uint32_t)(tid & 7) * 16u;

    const int arow_l = (lane & 7) + ((lane >> 3) & 1) * 8;
    const uint32_t a_lm0 = sb + (uint32_t)(32 * wM + arow_l) * 144u
                              + (uint32_t)(lane >> 4) * 16u;
    const int brow_l = (lane >> 4) * 8 + (lane & 7);
    const uint32_t b_lm0 = sb + (uint32_t)(128 + 32 * wN + brow_l) * 144u
                              + (uint32_t)((lane >> 3) & 1) * 16u;

    float acc[8][4];
#pragma unroll
    for (int i = 0; i < 8; i++) { acc[i][0] = acc[i][1] = acc[i][2] = acc[i][3] = 0.f; }

    const int nIter = K / GKH;

#define GEMM_ISSUE(IT, BUF) do {                                               \
        uint32_t _d = cdst + (uint32_t)((BUF) * GSTG_B);                       \
        _Pragma("unroll")                                                      \
        for (int _j = 0; _j < 4; _j++)                                         \
            cp_async16(_d + _j * (32u * 144u),                                 \
                       Abase + (size_t)(32 * _j) * K + (IT) * GKH);            \
        _Pragma("unroll")                                                      \
        for (int _j = 0; _j < 2; _j++)                                         \
            cp_async16(_d + (4 + _j) * (32u * 144u),                           \
                       Bbase + (size_t)(32 * _j) * K + (IT) * GKH);            \
        cp_commit();                                                           \
    } while (0)

    GEMM_ISSUE(0, 0);

    for (int it = 0; it < nIter; ++it) {
        cp_wait<0>();
        __syncthreads();

        if (it + 1 < nIter) GEMM_ISSUE(it + 1, (it + 1) & 1);

        const uint32_t a_lm = a_lm0 + (uint32_t)((it & 1) * GSTG_B);
        const uint32_t b_lm = b_lm0 + (uint32_t)((it & 1) * GSTG_B);

#pragma unroll
        for (int ks = 0; ks < 4; ks++) {
            uint32_t af[2][4], bf[4][2];
#pragma unroll
            for (int mt = 0; mt < 2; mt++)
                ldsm_x4(af[mt], a_lm + (uint32_t)(mt * 16 * 144 + ks * 32));
#pragma unroll
            for (int ng = 0; ng < 2; ng++) {
                uint32_t t4[4];
                ldsm_x4(t4, b_lm + (uint32_t)(ng * 16 * 144 + ks * 32));
                bf[2 * ng][0]     = t4[0];
                bf[2 * ng][1]     = t4[1];
                bf[2 * ng + 1][0] = t4[2];
                bf[2 * ng + 1][1] = t4[3];
            }
#pragma unroll
            for (int mt = 0; mt < 2; mt++)
#pragma unroll
                for (int nt = 0; nt < 4; nt++)
                    mma_f16(acc[mt * 4 + nt], af[mt], bf[nt]);
        }
    }

    if (out_half) {
        __half* C = (__half*)Cv;
#pragma unroll
        for (int mt = 0; mt < 2; mt++) {
            const int r0 = bm + 32 * wM + mt * 16 + g;
#pragma unroll
            for (int nt = 0; nt < 4; nt++) {
                const int col = bn + 32 * wN + nt * 8 + 2 * tig;
                *(__half2*)(C + (size_t)r0 * N + col) =
                    __floats2half2_rn(acc[mt * 4 + nt][0], acc[mt * 4 + nt][1]);
                *(__half2*)(C + (size_t)(r0 + 8) * N + col) =
                    __floats2half2_rn(acc[mt * 4 + nt][2], acc[mt * 4 + nt][3]);
            }
        }
    } else {
        float* C = (float*)Cv;
#pragma unroll
        for (int mt = 0; mt < 2; mt++) {
            const int r0 = bm + 32 * wM + mt * 16 + g;
#pragma unroll
            for (int nt = 0; nt < 4; nt++) {
                const int col = bn + 32 * wN + nt * 8 + 2 * tig;
                *(float2*)(C + (size_t)r0 * N + col) =
                    make_float2(acc[mt * 4 + nt][0], acc[mt * 4 + nt][1]);
                *(float2*)(C + (size_t)(r0 + 8) * N + col) =
                    make_float2(acc[mt * 4 + nt][2], acc[mt * 4 + nt][3]);
            }
        }
    }
#undef GEMM_ISSUE
}

// ---------------------------------------------------------------------------
// FP16 flash attention (unchanged from R13): max-free base-2 softmax (ex2),
// one barrier/iter, P/K/V double-buffered, PV(t) || S(t+1). 2 CTAs/SM.
// ---------------------------------------------------------------------------
#define BR 64
#define BC 64
#define NT (SEQ / BC)
#define AQ   0
#define AK0  17408
#define AK1  34816
#define AV0  52224
#define AV1  69632
#define AP0  87040
#define AP1  96256
#define APS  105472
#define ATTN_SMEM_BYTES 106496

__global__ __launch_bounds__(256, 2)
void attn_f16(const __half* __restrict__ xqkv, __half* __restrict__ xo)
{
    extern __shared__ char smc[];
    const uint32_t sb = (uint32_t)__cvta_generic_to_shared(smc);
    float* psum = (float*)(smc + APS);

    const int tid  = threadIdx.x;
    const int lane = tid & 31;
    const int wid  = tid >> 5;
    const int g    = lane >> 2;
    const int tig  = lane & 3;
    const int wM   = wid & 1;
    const int wN   = wid >> 1;

    const int h  = blockIdx.y;
    const int q0 = blockIdx.x * BR;

    const __half* Qg = xqkv + (size_t)q0 * QKV_N + h * HDIM;
    const __half* Kg = xqkv + 2048 + h * HDIM;
    const __half* Vg = xqkv + 4096 + h * HDIM;

    const int crow = tid >> 2;
    const int cbo  = (tid & 3) * 64;

    const int arow_l = (lane & 7) + ((lane >> 3) & 1) * 8;
    const uint32_t lpA272 = (uint32_t)arow_l * 272u + (uint32_t)(lane >> 4) * 16u;
    const uint32_t lpA144 = (uint32_t)arow_l * 144u + (uint32_t)(lane >> 4) * 16u;
    const int brow_l = (lane >> 4) * 8 + (lane & 7);
    const uint32_t lpB272 = (uint32_t)brow_l * 272u + (uint32_t)((lane >> 3) & 1) * 16u;

    const uint32_t q_lm   = sb + AQ + (uint32_t)(32 * wM) * 272u + lpA272;
    const uint32_t k_lmBo = (uint32_t)(16 * wN) * 272u + lpB272;
    const uint32_t p_lmBo = (uint32_t)(32 * wM) * 144u + lpA144;

    float sacc[4][4];
    float oacc[8][4];
    float lacc[2][2];
#pragma unroll
    for (int i = 0; i < 8; i++) { oacc[i][0] = oacc[i][1] = oacc[i][2] = oacc[i][3] = 0.f; }
    lacc[0][0] = lacc[0][1] = lacc[1][0] = lacc[1][1] = 0.f;

    auto compute_S = [&](uint32_t k_lm) {
#pragma unroll
        for (int i = 0; i < 4; i++) { sacc[i][0] = sacc[i][1] = sacc[i][2] = sacc[i][3] = 0.f; }
#pragma unroll
        for (int ks = 0; ks < 8; ks++) {
            uint32_t af[2][4], bf[2][2];
#pragma unroll
            for (int mt = 0; mt < 2; mt++)
                ldsm_x4(af[mt], q_lm + (uint32_t)(mt * 16 * 272 + ks * 32));
            {
                uint32_t t4[4];
                ldsm_x4(t4, k_lm + (uint32_t)(ks * 32));
                bf[0][0] = t4[0]; bf[0][1] = t4[1];
                bf[1][0] = t4[2]; bf[1][1] = t4[3];
            }
#pragma unroll
            for (int mt = 0; mt < 2; mt++)
#pragma unroll
                for (int nt = 0; nt < 2; nt++)
                    mma_f16(sacc[mt * 2 + nt], af[mt], bf[nt]);
        }
    };

    {
        const __half* qs = Qg + (size_t)crow * QKV_N + cbo / 2;
        const __half* ks = Kg + (size_t)crow * QKV_N + cbo / 2;
        const uint32_t qd = sb + AQ  + (uint32_t)crow * 272u + cbo;
        const uint32_t kd = sb + AK0 + (uint32_t)crow * 272u + cbo;
#pragma unroll
        for (int j = 0; j < 4; j++) cp_async16(qd + j * 16u, qs + j * 8);
#pragma unroll
        for (int j = 0; j < 4; j++) cp_async16(kd + j * 16u, ks + j * 8);
        cp_commit();

        const __half* vs = Vg + (size_t)crow * QKV_N + cbo / 2;
        const __half* k1 = Kg + (size_t)(BC + crow) * QKV_N + cbo / 2;
        const uint32_t vd = sb + AV0 + (uint32_t)crow * 272u + cbo;
        const uint32_t k1d = sb + AK1 + (uint32_t)crow * 272u + cbo;
#pragma unroll
        for (int j = 0; j < 4; j++) cp_async16(vd + j * 16u, vs + j * 8);
#pragma unroll
        for (int j = 0; j < 4; j++) cp_async16(k1d + j * 16u, k1 + j * 8);
        cp_commit();
    }

    cp_wait<1>();
    __syncthreads();

    compute_S(sb + AK0 + k_lmBo);

    for (int t = 0; t < NT; ++t) {
        const int cur = t & 1, nxt = cur ^ 1;
        const uint32_t pbuf = (cur ? AP1 : AP0);

        {
            char* pbase = smc + pbuf;
#pragma unroll
            for (int mt = 0; mt < 2; mt++)
#pragma unroll
                for (int hh = 0; hh < 2; hh++) {
                    const int r = 32 * wM + 16 * mt + g + 8 * hh;
                    float e0 = ex2(sacc[2 * mt][2 * hh]);
                    float e1 = ex2(sacc[2 * mt][2 * hh + 1]);
                    float e2 = ex2(sacc[2 * mt + 1][2 * hh]);
                    float e3 = ex2(sacc[2 * mt + 1][2 * hh + 1]);
                    lacc[mt][hh] += (e0 + e1) + (e2 + e3);
                    char* pr = pbase + (size_t)r * 144;
                    *(__half2*)(pr + (16 * wN + 2 * tig) * 2)     = __floats2half2_rn(e0, e1);
                    *(__half2*)(pr + (16 * wN + 8 + 2 * tig) * 2) = __floats2half2_rn(e2, e3);
                }
        }

        cp_wait<0>();
        __syncthreads();

        if (t + 1 < NT) {
            const __half* vs = Vg + (size_t)((t + 1) * BC + crow) * QKV_N + cbo / 2;
            const uint32_t vd = sb + (nxt ? AV1 : AV0) + (uint32_t)crow * 272u + cbo;
#pragma unroll
            for (int j = 0; j < 4; j++) cp_async16(vd + j * 16u, vs + j * 8);
            if (t + 2 < NT) {
                const __half* ks = Kg + (size_t)((t + 2) * BC + crow) * QKV_N + cbo / 2;
                const uint32_t kd = sb + (cur ? AK1 : AK0) + (uint32_t)crow * 272u + cbo;
#pragma unroll
                for (int j = 0; j < 4; j++) cp_async16(kd + j * 16u, ks + j * 8);
            }
            cp_commit();
        }

        const uint32_t p_lm = sb + pbuf + p_lmBo;
        const uint32_t v_lm = sb + (cur ? AV1 : AV0) + lpA272;
#pragma unroll
        for (int ks = 0; ks < 4; ks++) {
            uint32_t paf[2][4], vbf[4][2];
#pragma unroll
            for (int mt = 0; mt < 2; mt++)
                ldsm_x4(paf[mt], p_lm + (uint32_t)(mt * 16 * 144 + ks * 32));
#pragma unroll
            for (int ng = 0; ng < 2; ng++) {
                uint32_t t4[4];
                ldsm_x4_t(t4, v_lm + (uint32_t)(ks * 16 * 272 + (32 * wN + ng * 16) * 2));
                vbf[2 * ng][0]     = t4[0];
                vbf[2 * ng][1]     = t4[1];
                vbf[2 * ng + 1][0] = t4[2];
                vbf[2 * ng + 1][1] = t4[3];
            }
#pragma unroll
            for (int mt = 0; mt < 2; mt++)
#pragma unroll
                for (int nt = 0; nt < 4; nt++)
                    mma_f16(oacc[mt * 4 + nt], paf[mt], vbf[nt]);
        }

        if (t + 1 < NT)
            compute_S(sb + (nxt ? AK1 : AK0) + k_lmBo);
    }

#pragma unroll
    for (int mt = 0; mt < 2; mt++)
#pragma unroll
        for (int hh = 0; hh < 2; hh++) {
            float sum = lacc[mt][hh];
            sum += __shfl_xor_sync(0xffffffffu, sum, 1);
            sum += __shfl_xor_sync(0xffffffffu, sum, 2);
            if (tig == 0)
                psum[wN * 64 + 32 * wM + 16 * mt + g + 8 * hh] = sum;
        }
    __syncthreads();

#pragma unroll
    for (int mt = 0; mt < 2; mt++) {
        const int r0 = 32 * wM + 16 * mt + g;
        const float l0 = (psum[r0] + psum[64 + r0]) + (psum[128 + r0] + psum[192 + r0]);
        const float l1 = (psum[r0 + 8] + psum[64 + r0 + 8]) +
                         (psum[128 + r0 + 8] + psum[192 + r0 + 8]);
        const float il0 = 1.f / l0;
        const float il1 = 1.f / l1;
#pragma unroll
        for (int nt = 0; nt < 4; nt++) {
            const int col = h * HDIM + 32 * wN + 8 * nt + 2 * tig;
            *(__half2*)(xo + (size_t)(q0 + r0) * DIM + col) =
                __floats2half2_rn(oacc[mt * 4 + nt][0] * il0, oacc[mt * 4 + nt][1] * il0);
            *(__half2*)(xo + (size_t)(q0 + r0 + 8) * DIM + col) =
                __floats2half2_rn(oacc[mt * 4 + nt][2] * il1, oacc[mt * 4 + nt][3] * il1);
        }
    }
}

// ---------------------------------------------------------------------------
// Launch
// ---------------------------------------------------------------------------
extern "C" void kernel_launch(void* const* d_in, const int* in_sizes, int n_in,
                              void* d_out, int out_size)
{
    const float* x    = (const float*)d_in[0];   // [4096, 2048]
    const float* Wqkv = (const float*)d_in[1];   // [2048, 6144]
    const float* Wo   = (const float*)d_in[2];   // [2048, 2048]
    float* out = (float*)d_out;                  // [4096, 2048]

    __half *xh, *wqkvT, *woT, *xqkv, *xo;
    cudaGetSymbolAddress((void**)&xh,    g_xh);
    cudaGetSymbolAddress((void**)&wqkvT, g_wqkvT);
    cudaGetSymbolAddress((void**)&woT,   g_woT);
    cudaGetSymbolAddress((void**)&xqkv,  g_xqkv);
    cudaGetSymbolAddress((void**)&xo,    g_xo);

    cudaFuncSetAttribute(gemm_f16_big, cudaFuncAttributeMaxDynamicSharedMemorySize,
                         GEMMB_SMEM_BYTES);
    cudaFuncSetAttribute(gemm_f16, cudaFuncAttributeMaxDynamicSharedMemorySize,
                         GEMM_SMEM_BYTES);
    cudaFuncSetAttribute(attn_f16, cudaFuncAttributeMaxDynamicSharedMemorySize,
                         ATTN_SMEM_BYTES);

    // 0) prep: Wq pre-scaled by log2e/sqrt(d) -> base-2 softmax downstream
    f2h_kernel<<<(SEQ * DIM / 4) / 256, 256>>>(x, xh, SEQ * DIM / 4);
    {
        dim3 blk(32, 8);
        transpose_h_kernel<<<dim3(QKV_N / 32, DIM / 32), blk>>>(
            Wqkv, wqkvT, DIM, QKV_N, NHEADS * HDIM,
            0.08838834764831845f * 1.4426950408889634f);
        transpose_h_kernel<<<dim3(DIM / 32, DIM / 32), blk>>>(
            Wo, woT, DIM, DIM, 0, 1.0f);
    }
    // 1) xqkv = x @ Wqkv (fp16 out) — big tile, 2 CTAs/SM, 64-reg cap (fits)
    {
        dim3 grid(QKV_N / 128, SEQ / 128);
        gemm_f16_big<<<grid, 512, GEMMB_SMEM_BYTES>>>(xh, wqkvT, xqkv, QKV_N, DIM);
    }
    // 2) flash attention -> xo (fp16)
    {
        dim3 grid(SEQ / BR, NHEADS);
        attn_f16<<<grid, 256, ATTN_SMEM_BYTES>>>(xqkv, xo);
    }
    // 3) out = xo @ Wo (fp32 out) — 64-wide tile, 4 CTAs/SM
    {
        dim3 grid(DIM / 64, SEQ / 128);
        gemm_f16<<<grid, 256, GEMM_SMEM_BYTES>>>(xo, woT, out, DIM, DIM, 0);
    }
}